// round 16
// baseline (speedup 1.0000x reference)
#include <cuda_runtime.h>
#include <cstdint>

// MaxUnpooling2D: updates [16,64,64,256] f32, mask [16,64,64,256] i32 (flat idx
// into [16,128,128,256]), out [16,128,128,256] f32.
//
// FINAL — row-split scatter, 256 threads x 32768 blocks. Three harness
// samples: 63.49 / 63.68 / 64.00us (every other variant: 64.7-67.0us);
// kernel 59.1-59.7us, DRAM ~71% = 6.5 TB/s goodput on the irreducible
// 384MB traffic floor (output poisoned -> all 256MB must be written).
//
// Each pooled cell targets exactly one slot of its private 2x2 window -> no
// duplicate indices -> plain stores; zero-fill fused (thread writes both
// positions of one window ROW for its 4 channels, update in its slot, 0.0
// elsewhere). One thread = 4 channels x 1 window row (ry in {0,1}):
// 2x16B loads + 2x16B stores 1KB apart in a single output row; every warp
// access is a fully coalesced 512B transaction and each warp's stores stay
// within one output row. Sibling-row duplicate input reads hit L1/L2
// (verified: DRAM read traffic unchanged vs depth-1).
//
// Axes measured and closed: gather dataflow (-11us), per-thread depth /
// pipelining (regress), cache hints .cs/.nc (neutral), 256-bit accesses
// (neutral), block 512 (neutral), block 128 / 65536 blocks (slightly worse).

namespace {
constexpr int ROW   = 2 * 64 * 256;       // 32768  (dy=1 stride in out)
constexpr int COLS  = 256;                // dx=1 stride in out
constexpr int IMG   = 2 * 64 * ROW;       // batch stride in out
constexpr int NTHREADS_TOTAL = 16 * 64 * 64 * 2 * (256 / 4);  // 8,388,608
constexpr int THREADS = 256;
constexpr int BLOCKS  = NTHREADS_TOTAL / THREADS;             // 32768
}

__global__ void __launch_bounds__(THREADS, 8)
max_unpool_kernel(const float4* __restrict__ upd,
                  const int4*  __restrict__ mask,
                  float*       __restrict__ out)
{
    int t = blockIdx.x * THREADS + threadIdx.x;

    // t = (((b*64 + h)*64 + w)*2 + ry)*64 + c4
    int c4 = t & 63;
    int ry = (t >> 6) & 1;
    int w  = (t >> 7)  & 63;
    int h  = (t >> 13) & 63;
    int b  = t >> 19;
    int c  = c4 << 2;

    // Input group index (cell, c4): g = ((b*64+h)*64 + w)*64 + c4
    int g = ((t >> 7) << 6) | c4;

    // Window-origin flat index and this thread's row offset.
    int o00   = b * IMG + (h << 1) * ROW + (w << 1) * COLS + c;
    int sel   = ry * ROW;                 // 0 or ROW
    int obase = o00 + sel;

    float4 v = upd[g];
    int4   m = mask[g];

    // Per-lane offset within window: in {0, COLS, ROW, ROW+COLS}
    int d0 = m.x - o00;
    int d1 = m.y - o00 - 1;
    int d2 = m.z - o00 - 2;
    int d3 = m.w - o00 - 3;

    float4 rA = make_float4(d0 == sel        ? v.x : 0.f,
                            d1 == sel        ? v.y : 0.f,
                            d2 == sel        ? v.z : 0.f,
                            d3 == sel        ? v.w : 0.f);
    float4 rB = make_float4(d0 == sel + COLS ? v.x : 0.f,
                            d1 == sel + COLS ? v.y : 0.f,
                            d2 == sel + COLS ? v.z : 0.f,
                            d3 == sel + COLS ? v.w : 0.f);

    *reinterpret_cast<float4*>(out + obase)        = rA;
    *reinterpret_cast<float4*>(out + obase + COLS) = rB;
}

extern "C" void kernel_launch(void* const* d_in, const int* in_sizes, int n_in,
                              void* d_out, int out_size)
{
    const float4* upd  = reinterpret_cast<const float4*>(d_in[0]);
    const int4*   mask = reinterpret_cast<const int4*>(d_in[1]);
    float*        out  = reinterpret_cast<float*>(d_out);

    max_unpool_kernel<<<BLOCKS, THREADS>>>(upd, mask, out);
}

// round 17
// speedup vs baseline: 1.0292x; 1.0292x over previous
#include <cuda_runtime.h>
#include <cstdint>

// MaxUnpooling2D: updates [16,64,64,256] f32, mask [16,64,64,256] i32 (flat idx
// into [16,128,128,256]), out [16,128,128,256] f32.
//
// R17: champion structure (row-split scatter, 256thr x 32768blk; harness
// ledger 63.49/63.68/64.00/65.50us, kernel 59.1-60.2us, DRAM ~71%) with ONE
// experimental change: __stwt (write-through) on the output stores.
// Mechanism probed: default stores write-allocate in L2 -> dirty residency +
// bursty writeback interleaving against demand reads; .wt streams stores
// through without allocation, freeing L2 for the read stream and smoothing
// the DRAM R/W turnaround mix (the suspected cause of the 71% plateau).
// Full 128B sectors per warp -> no partial-sector write-through penalty.
// Best score (63.49) is banked; a neutral/negative result closes the last
// untested cache-policy axis at zero cost.

namespace {
constexpr int ROW   = 2 * 64 * 256;       // 32768  (dy=1 stride in out)
constexpr int COLS  = 256;                // dx=1 stride in out
constexpr int IMG   = 2 * 64 * ROW;       // batch stride in out
constexpr int NTHREADS_TOTAL = 16 * 64 * 64 * 2 * (256 / 4);  // 8,388,608
constexpr int THREADS = 256;
constexpr int BLOCKS  = NTHREADS_TOTAL / THREADS;             // 32768
}

__global__ void __launch_bounds__(THREADS, 8)
max_unpool_kernel(const float4* __restrict__ upd,
                  const int4*  __restrict__ mask,
                  float*       __restrict__ out)
{
    int t = blockIdx.x * THREADS + threadIdx.x;

    // t = (((b*64 + h)*64 + w)*2 + ry)*64 + c4
    int c4 = t & 63;
    int ry = (t >> 6) & 1;
    int w  = (t >> 7)  & 63;
    int h  = (t >> 13) & 63;
    int b  = t >> 19;
    int c  = c4 << 2;

    // Input group index (cell, c4): g = ((b*64+h)*64 + w)*64 + c4
    int g = ((t >> 7) << 6) | c4;

    // Window-origin flat index and this thread's row offset.
    int o00   = b * IMG + (h << 1) * ROW + (w << 1) * COLS + c;
    int sel   = ry * ROW;                 // 0 or ROW
    int obase = o00 + sel;

    float4 v = upd[g];
    int4   m = mask[g];

    // Per-lane offset within window: in {0, COLS, ROW, ROW+COLS}
    int d0 = m.x - o00;
    int d1 = m.y - o00 - 1;
    int d2 = m.z - o00 - 2;
    int d3 = m.w - o00 - 3;

    float4 rA = make_float4(d0 == sel        ? v.x : 0.f,
                            d1 == sel        ? v.y : 0.f,
                            d2 == sel        ? v.z : 0.f,
                            d3 == sel        ? v.w : 0.f);
    float4 rB = make_float4(d0 == sel + COLS ? v.x : 0.f,
                            d1 == sel + COLS ? v.y : 0.f,
                            d2 == sel + COLS ? v.z : 0.f,
                            d3 == sel + COLS ? v.w : 0.f);

    __stwt(reinterpret_cast<float4*>(out + obase),        rA);
    __stwt(reinterpret_cast<float4*>(out + obase + COLS), rB);
}

extern "C" void kernel_launch(void* const* d_in, const int* in_sizes, int n_in,
                              void* d_out, int out_size)
{
    const float4* upd  = reinterpret_cast<const float4*>(d_in[0]);
    const int4*   mask = reinterpret_cast<const int4*>(d_in[1]);
    float*        out  = reinterpret_cast<float*>(d_out);

    max_unpool_kernel<<<BLOCKS, THREADS>>>(upd, mask, out);
}